// round 2
// baseline (speedup 1.0000x reference)
#include <cuda_runtime.h>

// ---------------- problem constants ----------------
#define NN     100000
#define EE     1600000
#define ET     1700000          // EE + NN self loops
#define DIM    128
#define ODIM   64
#define GDIM   512              // 4*DIM
#define KLSTM  384              // h_tmp(128) | x(128) | h(128)
#define NEG_SLOPE 0.2f
#define RESW   0.5f

// ---------------- device scratch ----------------
__device__ float g_x0[NN * DIM];        // post-lin1 (residual inp)
__device__ float g_x [NN * DIM];        // current x
__device__ float g_xp[NN * DIM];        // GAT projected features
__device__ float g_ht[NN * DIM];        // tanh(GAT out)
__device__ float g_h [NN * DIM];        // LSTM h
__device__ float g_c [NN * DIM];        // LSTM c
__device__ float g_agg[NN * DIM];       // GAT aggregation
__device__ float g_gates[NN * GDIM];    // LSTM gates
__device__ float g_as[NN];
__device__ float g_ad[NN];
__device__ float g_den[NN];
__device__ float g_ex[ET];
__device__ float g_Wl1[DIM * DIM];          // lin1_w transposed -> [K=in][out]
__device__ float g_Wl2[DIM * ODIM];         // lin2_w transposed
__device__ float g_Wls[3 * KLSTM * GDIM];   // per-layer packed [384][512]

// ---------------- weight prep ----------------
__global__ void k_prep(const float* __restrict__ l1w, const float* __restrict__ l2w,
                       const float* __restrict__ wih, const float* __restrict__ whh) {
    const int TOT = 16384 + 8192 + 3 * KLSTM * GDIM;
    for (int i = blockIdx.x * blockDim.x + threadIdx.x; i < TOT; i += gridDim.x * blockDim.x) {
        if (i < 16384) {
            int k = i / 128, o = i % 128;              // g_Wl1[k*128+o] = l1w[o][k]
            g_Wl1[i] = l1w[o * 128 + k];
        } else if (i < 24576) {
            int t = i - 16384;
            int k = t / 64, o = t % 64;                // g_Wl2[k*64+o] = l2w[o][k]
            g_Wl2[t] = l2w[o * 128 + k];
        } else {
            int t = i - 24576;
            int l = t / (KLSTM * GDIM);
            int r = t % (KLSTM * GDIM);
            int k = r / GDIM, j = r % GDIM;            // g_Wls[l][k][j]
            g_Wls[t] = (k < 256) ? wih[l * GDIM * 256 + j * 256 + k]
                                 : whh[l * GDIM * 128 + j * 128 + (k - 256)];
        }
    }
}

// h = c = 0, x = x0 (run after lin1 GEMM)
__global__ void k_init_state() {
    for (int i = blockIdx.x * blockDim.x + threadIdx.x; i < NN * DIM; i += gridDim.x * blockDim.x) {
        g_h[i] = 0.f; g_c[i] = 0.f; g_x[i] = g_x0[i];
    }
}

__global__ void k_zero_layer() {
    for (int i = blockIdx.x * blockDim.x + threadIdx.x; i < NN * DIM; i += gridDim.x * blockDim.x) {
        g_agg[i] = 0.f;
        if (i < NN) g_den[i] = 0.f;
    }
}

// ---------------- GEMM: C[M,Nc] = A[M,K] @ B[K,Nc] (+bias) ----------------
// BM=128, BN=128, BK=8, 256 threads, 8x8 microtile.
// CAT=1: A columns gathered from A0|A1|A2 (each [M,128]).
template <int CAT>
__global__ __launch_bounds__(256) void gemm_kernel(
    const float* __restrict__ A0, const float* __restrict__ A1, const float* __restrict__ A2,
    const float* __restrict__ B, const float* __restrict__ bias, float* __restrict__ C,
    int M, int K, int Nc)
{
    __shared__ float sA[8][128];
    __shared__ float sB[8][128];
    const int tid = threadIdx.x;
    const int block_row = blockIdx.y * 128;
    const int block_col = blockIdx.x * 128;
    const int tx = tid & 15, ty = tid >> 4;

    const int a_row = tid >> 1;
    const int a_k4  = (tid & 1) * 4;
    const int b_k   = tid >> 5;
    const int b_c4  = (tid & 31) * 4;

    float acc[8][8];
#pragma unroll
    for (int i = 0; i < 8; i++)
#pragma unroll
        for (int j = 0; j < 8; j++) acc[i][j] = 0.f;

    for (int kt = 0; kt < K; kt += 8) {
        // A tile
        float4 av = make_float4(0.f, 0.f, 0.f, 0.f);
        int gr = block_row + a_row;
        if (gr < M) {
            int gk = kt + a_k4;
            const float* Ap;
            if (CAT) {
                if (gk < 128)      Ap = A0 + (size_t)gr * 128 + gk;
                else if (gk < 256) Ap = A1 + (size_t)gr * 128 + (gk - 128);
                else               Ap = A2 + (size_t)gr * 128 + (gk - 256);
            } else {
                Ap = A0 + (size_t)gr * K + gk;
            }
            av = *(const float4*)Ap;
        }
        sA[a_k4 + 0][a_row] = av.x;
        sA[a_k4 + 1][a_row] = av.y;
        sA[a_k4 + 2][a_row] = av.z;
        sA[a_k4 + 3][a_row] = av.w;
        // B tile
        float4 bv = make_float4(0.f, 0.f, 0.f, 0.f);
        int gc = block_col + b_c4;
        if (gc < Nc) bv = *(const float4*)(B + (size_t)(kt + b_k) * Nc + gc);
        *(float4*)&sB[b_k][b_c4] = bv;
        __syncthreads();

#pragma unroll
        for (int kk = 0; kk < 8; kk++) {
            float a[8], b[8];
            *(float4*)&a[0] = *(const float4*)&sA[kk][ty * 8];
            *(float4*)&a[4] = *(const float4*)&sA[kk][ty * 8 + 4];
            *(float4*)&b[0] = *(const float4*)&sB[kk][tx * 8];
            *(float4*)&b[4] = *(const float4*)&sB[kk][tx * 8 + 4];
#pragma unroll
            for (int i = 0; i < 8; i++)
#pragma unroll
                for (int j = 0; j < 8; j++) acc[i][j] += a[i] * b[j];
        }
        __syncthreads();
    }

#pragma unroll
    for (int i = 0; i < 8; i++) {
        int gr = block_row + ty * 8 + i;
        if (gr >= M) continue;
#pragma unroll
        for (int j = 0; j < 8; j += 4) {
            int gc = block_col + tx * 8 + j;
            if (gc >= Nc) continue;
            float4 v = make_float4(acc[i][j], acc[i][j + 1], acc[i][j + 2], acc[i][j + 3]);
            if (bias) { v.x += bias[gc]; v.y += bias[gc + 1]; v.z += bias[gc + 2]; v.w += bias[gc + 3]; }
            *(float4*)(C + (size_t)gr * Nc + gc) = v;
        }
    }
}

// ---------------- GAT attention ----------------
__global__ void k_alpha(const float* __restrict__ asv, const float* __restrict__ adv) {
    int warp = (blockIdx.x * blockDim.x + threadIdx.x) >> 5;
    int lane = threadIdx.x & 31;
    if (warp >= NN) return;
    float4 v = *(const float4*)(g_xp + (size_t)warp * 128 + lane * 4);
    float4 a = *(const float4*)(asv + lane * 4);
    float4 b = *(const float4*)(adv + lane * 4);
    float s1 = v.x * a.x + v.y * a.y + v.z * a.z + v.w * a.w;
    float s2 = v.x * b.x + v.y * b.y + v.z * b.z + v.w * b.w;
#pragma unroll
    for (int off = 16; off; off >>= 1) {
        s1 += __shfl_down_sync(0xffffffffu, s1, off);
        s2 += __shfl_down_sync(0xffffffffu, s2, off);
    }
    if (lane == 0) { g_as[warp] = s1; g_ad[warp] = s2; }
}

__global__ void k_edge1(const int* __restrict__ eidx) {
    int e = blockIdx.x * blockDim.x + threadIdx.x;
    if (e >= ET) return;
    int s, d;
    if (e < EE) { s = eidx[e]; d = eidx[EE + e]; }
    else        { s = d = e - EE; }
    float v = g_as[s] + g_ad[d];
    v = v >= 0.f ? v : NEG_SLOPE * v;         // leaky relu
    float ex = expf(v);                        // softmax is shift-invariant; |v| is small, skip max
    g_ex[e] = ex;
    atomicAdd(&g_den[d], ex);
}

__global__ void k_edge2(const int* __restrict__ eidx) {
    int warp = (blockIdx.x * blockDim.x + threadIdx.x) >> 5;
    if (warp >= ET) return;
    int lane = threadIdx.x & 31;
    int s, d;
    if (warp < EE) { s = eidx[warp]; d = eidx[EE + warp]; }
    else           { s = d = warp - EE; }
    float w = g_ex[warp] / (g_den[d] + 1e-16f);
    float4 v = *(const float4*)(g_xp + (size_t)s * 128 + lane * 4);
    v.x *= w; v.y *= w; v.z *= w; v.w *= w;
    atomicAdd((float4*)(g_agg + (size_t)d * 128 + lane * 4), v);
}

__global__ void k_tanh_bias(const float* __restrict__ bias) {
    int i = blockIdx.x * blockDim.x + threadIdx.x;
    if (i >= NN * DIM) return;
    g_ht[i] = tanhf(g_agg[i] + bias[i & 127]);
}

// ---------------- LSTM elementwise ----------------
__device__ __forceinline__ float sigf(float x) { return 1.f / (1.f + expf(-x)); }

__global__ void k_lstm() {
    int i = blockIdx.x * blockDim.x + threadIdx.x;
    if (i >= NN * DIM) return;
    int n = i >> 7, j = i & 127;
    size_t base = (size_t)n * GDIM + j;
    float ii = g_gates[base];
    float ff = g_gates[base + 128];
    float gg = g_gates[base + 256];
    float oo = g_gates[base + 384];
    float c = g_c[i];
    c = sigf(ff) * c + sigf(ii) * tanhf(gg);
    float h = sigf(oo) * tanhf(c);
    g_c[i] = c;
    g_h[i] = h;
    g_x[i] = h + RESW * g_x0[i];
}

// ---------------- final log_softmax (in place on d_out rows of 64) ----------------
__global__ void k_logsoftmax(float* __restrict__ out) {
    int warp = (blockIdx.x * blockDim.x + threadIdx.x) >> 5;
    int lane = threadIdx.x & 31;
    if (warp >= NN) return;
    float* row = out + (size_t)warp * ODIM;
    float v0 = row[lane], v1 = row[lane + 32];
    float m = fmaxf(v0, v1);
#pragma unroll
    for (int off = 16; off; off >>= 1) m = fmaxf(m, __shfl_xor_sync(0xffffffffu, m, off));
    float s = expf(v0 - m) + expf(v1 - m);
#pragma unroll
    for (int off = 16; off; off >>= 1) s += __shfl_xor_sync(0xffffffffu, s, off);
    float l = m + logf(s);
    row[lane] = v0 - l;
    row[lane + 32] = v1 - l;
}

// ---------------- launch ----------------
extern "C" void kernel_launch(void* const* d_in, const int* in_sizes, int n_in,
                              void* d_out, int out_size) {
    const float* x_in    = (const float*)d_in[0];
    const int*   eidx    = (const int*)  d_in[1];
    const float* lin1_w  = (const float*)d_in[2];
    const float* lin1_b  = (const float*)d_in[3];
    const float* gat_W   = (const float*)d_in[4];
    const float* att_src = (const float*)d_in[5];
    const float* att_dst = (const float*)d_in[6];
    const float* gat_b   = (const float*)d_in[7];
    const float* lstmWih = (const float*)d_in[8];
    const float* lstmWhh = (const float*)d_in[9];
    const float* lin2_w  = (const float*)d_in[10];
    const float* lin2_b  = (const float*)d_in[11];
    float* out = (float*)d_out;

    float *p_x0, *p_x, *p_xp, *p_ht, *p_h, *p_gates, *p_Wl1, *p_Wl2, *p_Wls;
    cudaGetSymbolAddress((void**)&p_x0,    g_x0);
    cudaGetSymbolAddress((void**)&p_x,     g_x);
    cudaGetSymbolAddress((void**)&p_xp,    g_xp);
    cudaGetSymbolAddress((void**)&p_ht,    g_ht);
    cudaGetSymbolAddress((void**)&p_h,     g_h);
    cudaGetSymbolAddress((void**)&p_gates, g_gates);
    cudaGetSymbolAddress((void**)&p_Wl1,   g_Wl1);
    cudaGetSymbolAddress((void**)&p_Wl2,   g_Wl2);
    cudaGetSymbolAddress((void**)&p_Wls,   g_Wls);

    const int T = 256;
    const int rowBlocks = (NN + 127) / 128;   // 782

    k_prep<<<1200, T>>>(lin1_w, lin2_w, lstmWih, lstmWhh);

    // lin1: x0 = x_in @ lin1_w.T + b
    gemm_kernel<0><<<dim3(1, rowBlocks), T>>>(x_in, nullptr, nullptr, p_Wl1, lin1_b, p_x0, NN, 128, 128);
    k_init_state<<<2048, T>>>();

    for (int l = 0; l < 3; l++) {
        // xp = x0 @ gat_W[l]
        gemm_kernel<0><<<dim3(1, rowBlocks), T>>>(p_x0, nullptr, nullptr,
                                                  gat_W + (size_t)l * 128 * 128, nullptr, p_xp,
                                                  NN, 128, 128);
        k_alpha<<<(NN * 32 + T - 1) / T, T>>>(att_src + l * 128, att_dst + l * 128);
        k_zero_layer<<<2048, T>>>();
        k_edge1<<<(ET + T - 1) / T, T>>>(eidx);
        k_edge2<<<(ET * 32 + T - 1) / T, T>>>(eidx);
        k_tanh_bias<<<(NN * DIM + T - 1) / T, T>>>(gat_b + l * 128);
        // gates = [ht | x | h] @ Wls[l]
        gemm_kernel<1><<<dim3(4, rowBlocks), T>>>(p_ht, p_x, p_h,
                                                  p_Wls + (size_t)l * KLSTM * GDIM, nullptr, p_gates,
                                                  NN, KLSTM, GDIM);
        k_lstm<<<(NN * DIM + T - 1) / T, T>>>();
    }

    // logits -> d_out, then log_softmax in place
    gemm_kernel<0><<<dim3(1, rowBlocks), T>>>(p_x, nullptr, nullptr, p_Wl2, lin2_b, out, NN, 128, ODIM);
    k_logsoftmax<<<(NN * 32 + T - 1) / T, T>>>(out);
}

// round 3
// speedup vs baseline: 1.9877x; 1.9877x over previous
#include <cuda_runtime.h>
#include <cstdint>

// ---------------- problem constants ----------------
#define NN     100000
#define EE     1600000
#define ET     1700000          // EE + NN self loops
#define DIM    128
#define ODIM   64
#define GDIM   512              // 4*DIM
#define KLSTM  384              // h_tmp(128) | x(128) | h(128)
#define NEG_SLOPE 0.2f
#define RESW   0.5f

// ---------------- device scratch ----------------
__device__ float g_x0[NN * DIM];
__device__ float g_x [NN * DIM];
__device__ float g_xp[NN * DIM];
__device__ float g_ht[NN * DIM];
__device__ float g_h [NN * DIM];
__device__ float g_c [NN * DIM];
__device__ float g_agg[NN * DIM];
__device__ float g_gates[NN * GDIM];
__device__ float g_as[NN];
__device__ float g_ad[NN];
__device__ float g_den[NN];
__device__ float g_ex[ET];
__device__ float g_Wl1[DIM * DIM];          // lin1_w transposed -> [K=in][out]
__device__ float g_Wl2[DIM * ODIM];         // lin2_w transposed
__device__ float g_Wls[3 * KLSTM * GDIM];   // per-layer packed [384][512]

// ---------------- weight prep ----------------
__global__ void k_prep(const float* __restrict__ l1w, const float* __restrict__ l2w,
                       const float* __restrict__ wih, const float* __restrict__ whh) {
    const int TOT = 16384 + 8192 + 3 * KLSTM * GDIM;
    for (int i = blockIdx.x * blockDim.x + threadIdx.x; i < TOT; i += gridDim.x * blockDim.x) {
        if (i < 16384) {
            int k = i / 128, o = i % 128;
            g_Wl1[i] = l1w[o * 128 + k];
        } else if (i < 24576) {
            int t = i - 16384;
            int k = t / 64, o = t % 64;
            g_Wl2[t] = l2w[o * 128 + k];
        } else {
            int t = i - 24576;
            int l = t / (KLSTM * GDIM);
            int r = t % (KLSTM * GDIM);
            int k = r / GDIM, j = r % GDIM;
            g_Wls[t] = (k < 256) ? wih[l * GDIM * 256 + j * 256 + k]
                                 : whh[l * GDIM * 128 + j * 128 + (k - 256)];
        }
    }
}

__global__ void k_init_state() {
    for (int i = blockIdx.x * blockDim.x + threadIdx.x; i < NN * DIM; i += gridDim.x * blockDim.x) {
        g_h[i] = 0.f; g_c[i] = 0.f; g_x[i] = g_x0[i];
    }
}

__global__ void k_zero_layer() {
    for (int i = blockIdx.x * blockDim.x + threadIdx.x; i < NN * DIM; i += gridDim.x * blockDim.x) {
        g_agg[i] = 0.f;
        if (i < NN) g_den[i] = 0.f;
    }
}

// ---------------- tf32 tensor-core GEMM ----------------
// C[M,Nc] = A[M,K] @ B[K,Nc] (+bias), BM=128, BN=128, BK=32.
// 256 threads = 8 warps as 2(M)x4(N); warp tile 64x32 via m16n8k8 tf32 mma.
// CAT=1: A columns gathered from A0|A1|A2 (each [M,128]); K segments align to 128.
__device__ __forceinline__ uint32_t f2tf32(float x) {
    uint32_t u;
    asm("cvt.rna.tf32.f32 %0, %1;" : "=r"(u) : "f"(x));
    return u;
}

template <int CAT>
__global__ __launch_bounds__(256) void tgemm(
    const float* __restrict__ A0, const float* __restrict__ A1, const float* __restrict__ A2,
    const float* __restrict__ B, const float* __restrict__ bias, float* __restrict__ C,
    int M, int K, int Nc)
{
    __shared__ float sA[128][36];   // [m][k], pad -> conflict-free frag loads
    __shared__ float sB[32][136];   // [k][n], pad 8 banks

    const int tid = threadIdx.x;
    const int wid = tid >> 5, lane = tid & 31;
    const int warpM = wid & 1, warpN = wid >> 1;           // 2 x 4 warps
    const int block_row = blockIdx.y * 128;
    const int block_col = blockIdx.x * 128;
    const int grp = lane >> 2, tig = lane & 3;             // groupID, thread-in-group

    float acc[4][4][4];
#pragma unroll
    for (int mi = 0; mi < 4; mi++)
#pragma unroll
        for (int ni = 0; ni < 4; ni++)
#pragma unroll
            for (int r = 0; r < 4; r++) acc[mi][ni][r] = 0.f;

    const int aRow = tid >> 3;          // 0..31
    const int aCol4 = (tid & 7) * 4;    // 0..28
    const int bRow = tid >> 5;          // 0..7
    const int bCol4 = (tid & 31) * 4;   // 0..124

    for (int kt = 0; kt < K; kt += 32) {
        // ---- load A tile (128 x 32) ----
        const float* Ap; int kb; int astride;
        if (CAT) {
            int seg = kt >> 7;
            Ap = (seg == 0) ? A0 : (seg == 1) ? A1 : A2;
            kb = kt & 127; astride = 128;
        } else { Ap = A0; kb = kt; astride = K; }
#pragma unroll
        for (int p = 0; p < 4; p++) {
            int r = aRow + p * 32;
            int gr = block_row + r;
            float4 v = make_float4(0.f, 0.f, 0.f, 0.f);
            if (gr < M) v = *(const float4*)(Ap + (size_t)gr * astride + kb + aCol4);
            *(float4*)&sA[r][aCol4] = v;
        }
        // ---- load B tile (32 x 128) ----
#pragma unroll
        for (int p = 0; p < 4; p++) {
            int r = bRow + p * 8;
            int gc = block_col + bCol4;
            float4 v = make_float4(0.f, 0.f, 0.f, 0.f);
            if (gc < Nc) v = *(const float4*)(B + (size_t)(kt + r) * Nc + gc);
            *(float4*)&sB[r][bCol4] = v;
        }
        __syncthreads();

#pragma unroll
        for (int kk = 0; kk < 32; kk += 8) {
            uint32_t af[4][4];
#pragma unroll
            for (int mi = 0; mi < 4; mi++) {
                int m = warpM * 64 + mi * 16;
                af[mi][0] = f2tf32(sA[m + grp    ][kk + tig    ]);
                af[mi][1] = f2tf32(sA[m + grp + 8][kk + tig    ]);
                af[mi][2] = f2tf32(sA[m + grp    ][kk + tig + 4]);
                af[mi][3] = f2tf32(sA[m + grp + 8][kk + tig + 4]);
            }
            uint32_t bf[4][2];
#pragma unroll
            for (int ni = 0; ni < 4; ni++) {
                int n = warpN * 32 + ni * 8;
                bf[ni][0] = f2tf32(sB[kk + tig    ][n + grp]);
                bf[ni][1] = f2tf32(sB[kk + tig + 4][n + grp]);
            }
#pragma unroll
            for (int mi = 0; mi < 4; mi++)
#pragma unroll
                for (int ni = 0; ni < 4; ni++) {
                    asm volatile(
                        "mma.sync.aligned.m16n8k8.row.col.f32.tf32.tf32.f32 "
                        "{%0,%1,%2,%3}, {%4,%5,%6,%7}, {%8,%9}, {%0,%1,%2,%3};"
                        : "+f"(acc[mi][ni][0]), "+f"(acc[mi][ni][1]),
                          "+f"(acc[mi][ni][2]), "+f"(acc[mi][ni][3])
                        : "r"(af[mi][0]), "r"(af[mi][1]), "r"(af[mi][2]), "r"(af[mi][3]),
                          "r"(bf[ni][0]), "r"(bf[ni][1]));
                }
        }
        __syncthreads();
    }

    // ---- epilogue ----
#pragma unroll
    for (int mi = 0; mi < 4; mi++) {
#pragma unroll
        for (int ni = 0; ni < 4; ni++) {
            int gr0 = block_row + warpM * 64 + mi * 16 + grp;
            int gc  = block_col + warpN * 32 + ni * 8 + 2 * tig;
            if (gc >= Nc) continue;
            float b0 = 0.f, b1 = 0.f;
            if (bias) { b0 = bias[gc]; b1 = bias[gc + 1]; }
            if (gr0 < M) {
                float2 v = make_float2(acc[mi][ni][0] + b0, acc[mi][ni][1] + b1);
                *(float2*)(C + (size_t)gr0 * Nc + gc) = v;
            }
            int gr1 = gr0 + 8;
            if (gr1 < M) {
                float2 v = make_float2(acc[mi][ni][2] + b0, acc[mi][ni][3] + b1);
                *(float2*)(C + (size_t)gr1 * Nc + gc) = v;
            }
        }
    }
}

// ---------------- GAT attention ----------------
__global__ void k_alpha(const float* __restrict__ asv, const float* __restrict__ adv) {
    int warp = (blockIdx.x * blockDim.x + threadIdx.x) >> 5;
    int lane = threadIdx.x & 31;
    if (warp >= NN) return;
    float4 v = *(const float4*)(g_xp + (size_t)warp * 128 + lane * 4);
    float4 a = *(const float4*)(asv + lane * 4);
    float4 b = *(const float4*)(adv + lane * 4);
    float s1 = v.x * a.x + v.y * a.y + v.z * a.z + v.w * a.w;
    float s2 = v.x * b.x + v.y * b.y + v.z * b.z + v.w * b.w;
#pragma unroll
    for (int off = 16; off; off >>= 1) {
        s1 += __shfl_down_sync(0xffffffffu, s1, off);
        s2 += __shfl_down_sync(0xffffffffu, s2, off);
    }
    if (lane == 0) { g_as[warp] = s1; g_ad[warp] = s2; }
}

__global__ void k_edge1(const int* __restrict__ eidx) {
    int e = blockIdx.x * blockDim.x + threadIdx.x;
    if (e >= ET) return;
    int s, d;
    if (e < EE) { s = eidx[e]; d = eidx[EE + e]; }
    else        { s = d = e - EE; }
    float v = g_as[s] + g_ad[d];
    v = v >= 0.f ? v : NEG_SLOPE * v;
    float ex = expf(v);                        // softmax shift-invariant; |v| small
    g_ex[e] = ex;
    atomicAdd(&g_den[d], ex);
}

__global__ void k_edge2(const int* __restrict__ eidx) {
    int warp = (blockIdx.x * blockDim.x + threadIdx.x) >> 5;
    if (warp >= ET) return;
    int lane = threadIdx.x & 31;
    int s, d;
    if (warp < EE) { s = eidx[warp]; d = eidx[EE + warp]; }
    else           { s = d = warp - EE; }
    float w = g_ex[warp] / (g_den[d] + 1e-16f);
    float4 v = *(const float4*)(g_xp + (size_t)s * 128 + lane * 4);
    v.x *= w; v.y *= w; v.z *= w; v.w *= w;
    atomicAdd((float4*)(g_agg + (size_t)d * 128 + lane * 4), v);
}

__global__ void k_tanh_bias(const float* __restrict__ bias) {
    int i = blockIdx.x * blockDim.x + threadIdx.x;
    if (i >= NN * DIM) return;
    g_ht[i] = tanhf(g_agg[i] + bias[i & 127]);
}

// ---------------- LSTM elementwise ----------------
__device__ __forceinline__ float sigf(float x) { return 1.f / (1.f + expf(-x)); }

__global__ void k_lstm() {
    int i = blockIdx.x * blockDim.x + threadIdx.x;
    if (i >= NN * DIM) return;
    int n = i >> 7, j = i & 127;
    size_t base = (size_t)n * GDIM + j;
    float ii = g_gates[base];
    float ff = g_gates[base + 128];
    float gg = g_gates[base + 256];
    float oo = g_gates[base + 384];
    float c = g_c[i];
    c = sigf(ff) * c + sigf(ii) * tanhf(gg);
    float h = sigf(oo) * tanhf(c);
    g_c[i] = c;
    g_h[i] = h;
    g_x[i] = h + RESW * g_x0[i];
}

// ---------------- final log_softmax ----------------
__global__ void k_logsoftmax(float* __restrict__ out) {
    int warp = (blockIdx.x * blockDim.x + threadIdx.x) >> 5;
    int lane = threadIdx.x & 31;
    if (warp >= NN) return;
    float* row = out + (size_t)warp * ODIM;
    float v0 = row[lane], v1 = row[lane + 32];
    float m = fmaxf(v0, v1);
#pragma unroll
    for (int off = 16; off; off >>= 1) m = fmaxf(m, __shfl_xor_sync(0xffffffffu, m, off));
    float s = expf(v0 - m) + expf(v1 - m);
#pragma unroll
    for (int off = 16; off; off >>= 1) s += __shfl_xor_sync(0xffffffffu, s, off);
    float l = m + logf(s);
    row[lane] = v0 - l;
    row[lane + 32] = v1 - l;
}

// ---------------- launch ----------------
extern "C" void kernel_launch(void* const* d_in, const int* in_sizes, int n_in,
                              void* d_out, int out_size) {
    const float* x_in    = (const float*)d_in[0];
    const int*   eidx    = (const int*)  d_in[1];
    const float* lin1_w  = (const float*)d_in[2];
    const float* lin1_b  = (const float*)d_in[3];
    const float* gat_W   = (const float*)d_in[4];
    const float* att_src = (const float*)d_in[5];
    const float* att_dst = (const float*)d_in[6];
    const float* gat_b   = (const float*)d_in[7];
    const float* lstmWih = (const float*)d_in[8];
    const float* lstmWhh = (const float*)d_in[9];
    const float* lin2_w  = (const float*)d_in[10];
    const float* lin2_b  = (const float*)d_in[11];
    float* out = (float*)d_out;

    float *p_x0, *p_x, *p_xp, *p_ht, *p_h, *p_gates, *p_Wl1, *p_Wl2, *p_Wls;
    cudaGetSymbolAddress((void**)&p_x0,    g_x0);
    cudaGetSymbolAddress((void**)&p_x,     g_x);
    cudaGetSymbolAddress((void**)&p_xp,    g_xp);
    cudaGetSymbolAddress((void**)&p_ht,    g_ht);
    cudaGetSymbolAddress((void**)&p_h,     g_h);
    cudaGetSymbolAddress((void**)&p_gates, g_gates);
    cudaGetSymbolAddress((void**)&p_Wl1,   g_Wl1);
    cudaGetSymbolAddress((void**)&p_Wl2,   g_Wl2);
    cudaGetSymbolAddress((void**)&p_Wls,   g_Wls);

    const int T = 256;
    const int rowBlocks = (NN + 127) / 128;   // 782

    k_prep<<<1200, T>>>(lin1_w, lin2_w, lstmWih, lstmWhh);

    // lin1: x0 = x_in @ lin1_w.T + b
    tgemm<0><<<dim3(1, rowBlocks), T>>>(x_in, nullptr, nullptr, p_Wl1, lin1_b, p_x0, NN, 128, 128);
    k_init_state<<<2048, T>>>();

    for (int l = 0; l < 3; l++) {
        tgemm<0><<<dim3(1, rowBlocks), T>>>(p_x0, nullptr, nullptr,
                                            gat_W + (size_t)l * 128 * 128, nullptr, p_xp,
                                            NN, 128, 128);
        k_alpha<<<(NN * 32 + T - 1) / T, T>>>(att_src + l * 128, att_dst + l * 128);
        k_zero_layer<<<2048, T>>>();
        k_edge1<<<(ET + T - 1) / T, T>>>(eidx);
        k_edge2<<<(ET * 32 + T - 1) / T, T>>>(eidx);
        k_tanh_bias<<<(NN * DIM + T - 1) / T, T>>>(gat_b + l * 128);
        tgemm<1><<<dim3(4, rowBlocks), T>>>(p_ht, p_x, p_h,
                                            p_Wls + (size_t)l * KLSTM * GDIM, nullptr, p_gates,
                                            NN, KLSTM, GDIM);
        k_lstm<<<(NN * DIM + T - 1) / T, T>>>();
    }

    tgemm<0><<<dim3(1, rowBlocks), T>>>(p_x, nullptr, nullptr, p_Wl2, lin2_b, out, NN, 128, ODIM);
    k_logsoftmax<<<(NN * 32 + T - 1) / T, T>>>(out);
}

// round 4
// speedup vs baseline: 2.1430x; 1.0782x over previous
#include <cuda_runtime.h>
#include <cstdint>

// ---------------- problem constants ----------------
#define NN     100000
#define EE     1600000
#define ET     1700000          // EE + NN self loops
#define DIM    128
#define ODIM   64
#define GDIM   512              // 4*DIM
#define KLSTM  384              // h_tmp(128) | x(128) | h(128)
#define NEG_SLOPE 0.2f
#define RESW   0.5f

// ---------------- device scratch ----------------
__device__ float g_x0[NN * DIM];
__device__ float g_x [NN * DIM];
__device__ float g_xp[NN * DIM];
__device__ float g_ht[NN * DIM];
__device__ float g_h [NN * DIM];
__device__ float g_c [NN * DIM];
__device__ float g_agg[NN * DIM];
__device__ float g_gates[NN * GDIM];
__device__ float g_as[NN];
__device__ float g_ad[NN];
__device__ float g_den[NN];
__device__ float g_ex[ET];
__device__ float g_Wl1[DIM * DIM];          // lin1_w transposed -> [K=in][out]
__device__ float g_Wl2[DIM * ODIM];         // lin2_w transposed
__device__ float g_Wls[3 * KLSTM * GDIM];   // per-layer packed [384][512]

// ---------------- weight prep ----------------
__global__ void k_prep(const float* __restrict__ l1w, const float* __restrict__ l2w,
                       const float* __restrict__ wih, const float* __restrict__ whh) {
    const int TOT = 16384 + 8192 + 3 * KLSTM * GDIM;
    for (int i = blockIdx.x * blockDim.x + threadIdx.x; i < TOT; i += gridDim.x * blockDim.x) {
        if (i < 16384) {
            int k = i / 128, o = i % 128;
            g_Wl1[i] = l1w[o * 128 + k];
        } else if (i < 24576) {
            int t = i - 16384;
            int k = t / 64, o = t % 64;
            g_Wl2[t] = l2w[o * 128 + k];
        } else {
            int t = i - 24576;
            int l = t / (KLSTM * GDIM);
            int r = t % (KLSTM * GDIM);
            int k = r / GDIM, j = r % GDIM;
            g_Wls[t] = (k < 256) ? wih[l * GDIM * 256 + j * 256 + k]
                                 : whh[l * GDIM * 128 + j * 128 + (k - 256)];
        }
    }
}

__global__ void k_init_state() {
    for (int i = blockIdx.x * blockDim.x + threadIdx.x; i < NN * DIM; i += gridDim.x * blockDim.x) {
        g_h[i] = 0.f; g_c[i] = 0.f; g_x[i] = g_x0[i];
    }
}

__global__ void k_zero_agg() {
    for (int i = blockIdx.x * blockDim.x + threadIdx.x; i < NN * DIM; i += gridDim.x * blockDim.x)
        g_agg[i] = 0.f;
}

// ---------------- tf32 tensor-core GEMM, cp.async double-buffered ----------------
// C[M,Nc] = A[M,K] @ B[K,Nc] (+bias). BM=128, BN=128, BK=16, 256 threads,
// 8 warps 2(M)x4(N), warp tile 64x32, m16n8k8 tf32 mma with raw-fp32 operands
// (HW reads tf32 bits only -> truncation; fine at our error budget).
// CAT=1: A columns gathered from A0|A1|A2 (each [M,128]).
#define BKT 16

__device__ __forceinline__ void cp16(uint32_t dst, const void* src, int sz) {
    asm volatile("cp.async.cg.shared.global [%0], [%1], 16, %2;\n"
                 :: "r"(dst), "l"(src), "r"(sz));
}

template <int CAT>
__global__ __launch_bounds__(256) void tgemm(
    const float* __restrict__ A0, const float* __restrict__ A1, const float* __restrict__ A2,
    const float* __restrict__ B, const float* __restrict__ bias, float* __restrict__ C,
    int M, int K, int Nc)
{
    __shared__ float sA[2][128][20];   // [m][k], stride 20 -> conflict-free frags
    __shared__ float sB[2][BKT][136];  // [k][n], stride 136

    const int tid = threadIdx.x;
    const int wid = tid >> 5, lane = tid & 31;
    const int warpM = wid & 1, warpN = wid >> 1;
    const int block_row = blockIdx.y * 128;
    const int block_col = blockIdx.x * 128;
    const int grp = lane >> 2, tig = lane & 3;

    float acc[4][4][4];
#pragma unroll
    for (int mi = 0; mi < 4; mi++)
#pragma unroll
        for (int ni = 0; ni < 4; ni++)
#pragma unroll
            for (int r = 0; r < 4; r++) acc[mi][ni][r] = 0.f;

    const int a_m = tid >> 1;            // 0..127 (p adds 0/... see below)
    const int nKt = K / BKT;

    // A: 128x16 floats = 512 16B-chunks; thread does 2: i = tid + p*256 -> m=i>>2, kc=i&3
    // B: 16x128 floats = 512 chunks;    thread does 2: i = tid + p*256 -> kr=i>>5, nc=i&31
    auto load_stage = [&](int stage, int kt) {
        const float* Ap; int kb, astride;
        if (CAT) {
            int seg = kt >> 7;
            Ap = (seg == 0) ? A0 : (seg == 1) ? A1 : A2;
            kb = kt & 127; astride = 128;
        } else { Ap = A0; kb = kt; astride = K; }
#pragma unroll
        for (int p = 0; p < 2; p++) {
            int i = tid + p * 256;
            int m = i >> 2, kc = i & 3;
            int gr = block_row + m;
            uint32_t dst = (uint32_t)__cvta_generic_to_shared(&sA[stage][m][kc * 4]);
            const float* src = Ap + (size_t)gr * astride + kb + kc * 4;
            cp16(dst, src, gr < M ? 16 : 0);
        }
#pragma unroll
        for (int p = 0; p < 2; p++) {
            int i = tid + p * 256;
            int kr = i >> 5, nc = i & 31;
            int gc = block_col + nc * 4;
            uint32_t dst = (uint32_t)__cvta_generic_to_shared(&sB[stage][kr][nc * 4]);
            const float* src = B + (size_t)(kt + kr) * Nc + gc;
            cp16(dst, src, gc < Nc ? 16 : 0);
        }
        asm volatile("cp.async.commit_group;\n");
    };

    load_stage(0, 0);

    for (int it = 0; it < nKt; it++) {
        if (it + 1 < nKt) {
            load_stage((it + 1) & 1, (it + 1) * BKT);
            asm volatile("cp.async.wait_group 1;\n");
        } else {
            asm volatile("cp.async.wait_group 0;\n");
        }
        __syncthreads();

        const int s = it & 1;
#pragma unroll
        for (int kk = 0; kk < BKT; kk += 8) {
            uint32_t af[4][4];
#pragma unroll
            for (int mi = 0; mi < 4; mi++) {
                int m = warpM * 64 + mi * 16;
                af[mi][0] = __float_as_uint(sA[s][m + grp    ][kk + tig    ]);
                af[mi][1] = __float_as_uint(sA[s][m + grp + 8][kk + tig    ]);
                af[mi][2] = __float_as_uint(sA[s][m + grp    ][kk + tig + 4]);
                af[mi][3] = __float_as_uint(sA[s][m + grp + 8][kk + tig + 4]);
            }
            uint32_t bf[4][2];
#pragma unroll
            for (int ni = 0; ni < 4; ni++) {
                int n = warpN * 32 + ni * 8;
                bf[ni][0] = __float_as_uint(sB[s][kk + tig    ][n + grp]);
                bf[ni][1] = __float_as_uint(sB[s][kk + tig + 4][n + grp]);
            }
#pragma unroll
            for (int mi = 0; mi < 4; mi++)
#pragma unroll
                for (int ni = 0; ni < 4; ni++) {
                    asm volatile(
                        "mma.sync.aligned.m16n8k8.row.col.f32.tf32.tf32.f32 "
                        "{%0,%1,%2,%3}, {%4,%5,%6,%7}, {%8,%9}, {%0,%1,%2,%3};"
                        : "+f"(acc[mi][ni][0]), "+f"(acc[mi][ni][1]),
                          "+f"(acc[mi][ni][2]), "+f"(acc[mi][ni][3])
                        : "r"(af[mi][0]), "r"(af[mi][1]), "r"(af[mi][2]), "r"(af[mi][3]),
                          "r"(bf[ni][0]), "r"(bf[ni][1]));
                }
        }
        __syncthreads();
    }

    // ---- epilogue ----
#pragma unroll
    for (int mi = 0; mi < 4; mi++) {
#pragma unroll
        for (int ni = 0; ni < 4; ni++) {
            int gr0 = block_row + warpM * 64 + mi * 16 + grp;
            int gc  = block_col + warpN * 32 + ni * 8 + 2 * tig;
            if (gc >= Nc) continue;
            float b0 = 0.f, b1 = 0.f;
            if (bias) { b0 = bias[gc]; b1 = bias[gc + 1]; }
            if (gr0 < M) {
                float2 v = make_float2(acc[mi][ni][0] + b0, acc[mi][ni][1] + b1);
                *(float2*)(C + (size_t)gr0 * Nc + gc) = v;
            }
            int gr1 = gr0 + 8;
            if (gr1 < M) {
                float2 v = make_float2(acc[mi][ni][2] + b0, acc[mi][ni][3] + b1);
                *(float2*)(C + (size_t)gr1 * Nc + gc) = v;
            }
        }
    }
    (void)a_m;
}

// ---------------- GAT attention ----------------
__global__ void k_alpha(const float* __restrict__ asv, const float* __restrict__ adv) {
    int warp = (blockIdx.x * blockDim.x + threadIdx.x) >> 5;
    int lane = threadIdx.x & 31;
    if (warp >= NN) return;
    float4 v = *(const float4*)(g_xp + (size_t)warp * 128 + lane * 4);
    float4 a = *(const float4*)(asv + lane * 4);
    float4 b = *(const float4*)(adv + lane * 4);
    float s1 = v.x * a.x + v.y * a.y + v.z * a.z + v.w * a.w;
    float s2 = v.x * b.x + v.y * b.y + v.z * b.z + v.w * b.w;
#pragma unroll
    for (int off = 16; off; off >>= 1) {
        s1 += __shfl_down_sync(0xffffffffu, s1, off);
        s2 += __shfl_down_sync(0xffffffffu, s2, off);
    }
    if (lane == 0) { g_as[warp] = s1; g_ad[warp] = s2; g_den[warp] = 0.f; }
}

__global__ void k_edge1(const int* __restrict__ eidx) {
    int e = blockIdx.x * blockDim.x + threadIdx.x;
    if (e >= ET) return;
    int s, d;
    if (e < EE) { s = eidx[e]; d = eidx[EE + e]; }
    else        { s = d = e - EE; }
    float v = g_as[s] + g_ad[d];
    v = v >= 0.f ? v : NEG_SLOPE * v;
    float ex = expf(v);                        // softmax shift-invariant; |v| small
    g_ex[e] = ex;
    atomicAdd(&g_den[d], ex);
}

__global__ void k_edge2(const int* __restrict__ eidx) {
    int warp = (blockIdx.x * blockDim.x + threadIdx.x) >> 5;
    if (warp >= ET) return;
    int lane = threadIdx.x & 31;
    int s, d;
    if (warp < EE) { s = eidx[warp]; d = eidx[EE + warp]; }
    else           { s = d = warp - EE; }
    float w = g_ex[warp] / (g_den[d] + 1e-16f);
    float4 v = *(const float4*)(g_xp + (size_t)s * 128 + lane * 4);
    v.x *= w; v.y *= w; v.z *= w; v.w *= w;
    atomicAdd((float4*)(g_agg + (size_t)d * 128 + lane * 4), v);
}

__global__ void k_tanh_bias(const float* __restrict__ bias) {
    int i = blockIdx.x * blockDim.x + threadIdx.x;
    if (i >= NN * DIM) return;
    g_ht[i] = tanhf(g_agg[i] + bias[i & 127]);
}

// ---------------- LSTM elementwise ----------------
__device__ __forceinline__ float sigf(float x) { return 1.f / (1.f + expf(-x)); }

__global__ void k_lstm() {
    int i = blockIdx.x * blockDim.x + threadIdx.x;
    if (i >= NN * DIM) return;
    int n = i >> 7, j = i & 127;
    size_t base = (size_t)n * GDIM + j;
    float ii = g_gates[base];
    float ff = g_gates[base + 128];
    float gg = g_gates[base + 256];
    float oo = g_gates[base + 384];
    float c = g_c[i];
    c = sigf(ff) * c + sigf(ii) * tanhf(gg);
    float h = sigf(oo) * tanhf(c);
    g_c[i] = c;
    g_h[i] = h;
    g_x[i] = h + RESW * g_x0[i];
}

// ---------------- final log_softmax ----------------
__global__ void k_logsoftmax(float* __restrict__ out) {
    int warp = (blockIdx.x * blockDim.x + threadIdx.x) >> 5;
    int lane = threadIdx.x & 31;
    if (warp >= NN) return;
    float* row = out + (size_t)warp * ODIM;
    float v0 = row[lane], v1 = row[lane + 32];
    float m = fmaxf(v0, v1);
#pragma unroll
    for (int off = 16; off; off >>= 1) m = fmaxf(m, __shfl_xor_sync(0xffffffffu, m, off));
    float s = expf(v0 - m) + expf(v1 - m);
#pragma unroll
    for (int off = 16; off; off >>= 1) s += __shfl_xor_sync(0xffffffffu, s, off);
    float l = m + logf(s);
    row[lane] = v0 - l;
    row[lane + 32] = v1 - l;
}

// ---------------- launch ----------------
extern "C" void kernel_launch(void* const* d_in, const int* in_sizes, int n_in,
                              void* d_out, int out_size) {
    const float* x_in    = (const float*)d_in[0];
    const int*   eidx    = (const int*)  d_in[1];
    const float* lin1_w  = (const float*)d_in[2];
    const float* lin1_b  = (const float*)d_in[3];
    const float* gat_W   = (const float*)d_in[4];
    const float* att_src = (const float*)d_in[5];
    const float* att_dst = (const float*)d_in[6];
    const float* gat_b   = (const float*)d_in[7];
    const float* lstmWih = (const float*)d_in[8];
    const float* lstmWhh = (const float*)d_in[9];
    const float* lin2_w  = (const float*)d_in[10];
    const float* lin2_b  = (const float*)d_in[11];
    float* out = (float*)d_out;

    float *p_x0, *p_x, *p_xp, *p_ht, *p_h, *p_gates, *p_Wl1, *p_Wl2, *p_Wls;
    cudaGetSymbolAddress((void**)&p_x0,    g_x0);
    cudaGetSymbolAddress((void**)&p_x,     g_x);
    cudaGetSymbolAddress((void**)&p_xp,    g_xp);
    cudaGetSymbolAddress((void**)&p_ht,    g_ht);
    cudaGetSymbolAddress((void**)&p_h,     g_h);
    cudaGetSymbolAddress((void**)&p_gates, g_gates);
    cudaGetSymbolAddress((void**)&p_Wl1,   g_Wl1);
    cudaGetSymbolAddress((void**)&p_Wl2,   g_Wl2);
    cudaGetSymbolAddress((void**)&p_Wls,   g_Wls);

    const int T = 256;
    const int rowBlocks = (NN + 127) / 128;   // 782

    k_prep<<<1200, T>>>(lin1_w, lin2_w, lstmWih, lstmWhh);

    tgemm<0><<<dim3(1, rowBlocks), T>>>(x_in, nullptr, nullptr, p_Wl1, lin1_b, p_x0, NN, 128, 128);
    k_init_state<<<2048, T>>>();

    for (int l = 0; l < 3; l++) {
        tgemm<0><<<dim3(1, rowBlocks), T>>>(p_x0, nullptr, nullptr,
                                            gat_W + (size_t)l * 128 * 128, nullptr, p_xp,
                                            NN, 128, 128);
        k_alpha<<<(NN * 32 + T - 1) / T, T>>>(att_src + l * 128, att_dst + l * 128);
        k_zero_agg<<<2048, T>>>();
        k_edge1<<<(ET + T - 1) / T, T>>>(eidx);
        k_edge2<<<(ET * 32 + T - 1) / T, T>>>(eidx);
        k_tanh_bias<<<(NN * DIM + T - 1) / T, T>>>(gat_b + l * 128);
        tgemm<1><<<dim3(4, rowBlocks), T>>>(p_ht, p_x, p_h,
                                            p_Wls + (size_t)l * KLSTM * GDIM, nullptr, p_gates,
                                            NN, KLSTM, GDIM);
        k_lstm<<<(NN * DIM + T - 1) / T, T>>>();
    }

    tgemm<0><<<dim3(1, rowBlocks), T>>>(p_x, nullptr, nullptr, p_Wl2, lin2_b, out, NN, 128, ODIM);
    k_logsoftmax<<<(NN * 32 + T - 1) / T, T>>>(out);
}